// round 8
// baseline (speedup 1.0000x reference)
#include <cuda_runtime.h>
#include <cstdint>

// CausalMemoryAttention: B=16, S=4096, D=1024   (exact restructure, validated)
//   qt = (query@Wq^T + bq)@Wk ; qbk = query.(Wq^T.bk) + bq.bk
//   score[b,s] = (mb[b,s].qt[b] + qbk[b])/32 * tw[b,s],  tw = exp(-0.01*(ct-ts))
//   p = exp(score); attn = p/E; m = (sum p*mb)/E; attended = m@Wv^T + bv
// 3 launches, NO inter-block synchronization anywhere:
//   k_pre  (qt via redundant Q chunks, u = Wq^T.bk, tw)        144 blocks
//   k_main (268MB pass, per-warp cp.async pipelines; last CTA per b -> m, 1/E)
//   k_post (attended GEMM + attn normalize)

#define B 16
#define S 4096
#define D 1024
#define D4 256
#define QT_SPLITS 16
#define CTAS_PER_B 18
#define NCTA_MAIN (B * CTAS_PER_B)        // 288 (single wave at 2 CTA/SM)
#define WDEPTH 3                          // per-warp pipeline depth (rows)
#define ROW_F4 256                        // one row = 4KB = 256 float4
#define SMEM_MAIN (8 * WDEPTH * ROW_F4 * 16)   // 96 KB

// -------- scratch (device globals; counter self-resets) --------
__device__ __align__(16) float g_qt_part[QT_SPLITS * B * D];
__device__ __align__(16) float g_u_part[4 * D];
__device__ __align__(16) float g_tw[B * S];
__device__ __align__(16) float g_p[B * S];
__device__ __align__(16) float g_macc[NCTA_MAIN * D];
__device__ float g_Epart[NCTA_MAIN];
__device__ __align__(16) float g_m[B * D];
__device__ float g_inv[B];
__device__ int g_cnt[B];      // k_main CTAs done per b (arrive-only, no spin)

// ---------------- cp.async helpers ----------------
// NOTE: "memory" clobber is load-bearing — the barrier-free mainloop relies on
// program order between the smem v[] loads and the same-slot cp.async refill.
__device__ __forceinline__ void cp_async16(uint32_t smem, const void* gmem) {
    asm volatile("cp.async.cg.shared.global [%0], [%1], 16;"
                 :: "r"(smem), "l"(gmem) : "memory");
}
__device__ __forceinline__ void cp_commit() {
    asm volatile("cp.async.commit_group;" ::: "memory");
}
template <int N> __device__ __forceinline__ void cp_wait() {
    asm volatile("cp.async.wait_group %0;" :: "n"(N) : "memory");
}

// ============================================================
// k_pre: 144 independent blocks x 256 threads.
//   bid 0..63 : qt-role. block = (e-tile of 256, d-chunk of 64).
//               Recomputes its Q chunk (query@Wq^T+bq) locally, then
//               qt partial for its d-chunk -> g_qt_part. No waiting.
//   bid 64..79: u-role. u[e] partial = sum_{d in 256-chunk} Wq[d,e]*bk[d].
//   bid 80..143: tw-role. tw = exp(-0.01*(ct-ts)).
// ============================================================
__global__ __launch_bounds__(256) void k_pre(
    const float* __restrict__ query, const float* __restrict__ Wq,
    const float* __restrict__ bq, const float* __restrict__ Wk,
    const float* __restrict__ bk,
    const float* __restrict__ ts, const float* __restrict__ ct)
{
    int bid = blockIdx.x, tid = threadIdx.x;

    if (bid < 64) {
        // ---------------- qt-role ----------------
        __shared__ __align__(16) float Qs[64 * 16];
        int e = (bid & 3) * 256 + tid;     // e in 0..1023
        int by = bid >> 2;                 // d-chunk 0..15
        int d0 = by * 64;
        int warp = tid >> 5, lane = tid & 31;

        // redundantly compute Q[:, d0..d0+63]: warp handles 8 d-columns
        const float4* X4 = reinterpret_cast<const float4*>(query);
        for (int r = 0; r < 8; r++) {
            int dl = warp * 8 + r, d = d0 + dl;
            const float4* W4 = reinterpret_cast<const float4*>(Wq) + (size_t)d * D4;
            float4 w[8];
#pragma unroll
            for (int k = 0; k < 8; k++) w[k] = W4[k * 32 + lane];
            float bb = bq[d];
#pragma unroll
            for (int b = 0; b < B; b += 2) {
                float sa = 0.f, sb = 0.f;
#pragma unroll
                for (int k = 0; k < 8; k++) {
                    float4 xa = X4[b * D4 + k * 32 + lane];
                    float4 xb = X4[(b + 1) * D4 + k * 32 + lane];
                    sa += xa.x * w[k].x; sa += xa.y * w[k].y;
                    sa += xa.z * w[k].z; sa += xa.w * w[k].w;
                    sb += xb.x * w[k].x; sb += xb.y * w[k].y;
                    sb += xb.z * w[k].z; sb += xb.w * w[k].w;
                }
#pragma unroll
                for (int o = 16; o > 0; o >>= 1) {
                    sa += __shfl_xor_sync(0xffffffffu, sa, o);
                    sb += __shfl_xor_sync(0xffffffffu, sb, o);
                }
                if (lane == 0) {
                    Qs[dl * 16 + b] = sa + bb;
                    Qs[dl * 16 + b + 1] = sb + bb;
                }
            }
        }
        __syncthreads();

        float acc[16];
#pragma unroll
        for (int bb = 0; bb < 16; bb++) acc[bb] = 0.f;
#pragma unroll 8
        for (int dl = 0; dl < 64; dl++) {
            float wv = Wk[(size_t)(d0 + dl) * D + e];
            const float4* q4 = reinterpret_cast<const float4*>(&Qs[dl * 16]);
#pragma unroll
            for (int jj = 0; jj < 4; jj++) {
                float4 qq = q4[jj];
                acc[4 * jj + 0] += qq.x * wv;
                acc[4 * jj + 1] += qq.y * wv;
                acc[4 * jj + 2] += qq.z * wv;
                acc[4 * jj + 3] += qq.w * wv;
            }
        }
#pragma unroll
        for (int bb = 0; bb < 16; bb++)
            g_qt_part[(size_t)(by * 16 + bb) * D + e] = acc[bb];
    } else if (bid < 80) {
        // ---------------- u-role: u[e] = sum_d Wq[d,e]*bk[d] (d-split 4) ----
        int q = bid - 64;
        int e = (q & 3) * 256 + tid;
        int dp = q >> 2;                 // 0..3
        int dbase = dp * 256;
        float s = 0.f;
#pragma unroll 8
        for (int d = 0; d < 256; d++)
            s += Wq[(size_t)(dbase + d) * D + e] * bk[dbase + d];
        g_u_part[dp * D + e] = s;
    } else {
        // ---------------- tw-role ----------------
        int idx = (bid - 80) * 1024 + tid * 4;
        int b = idx >> 12;
        float curt = ct[b];
        float4 t = *reinterpret_cast<const float4*>(ts + idx);
        float4 w;
        w.x = __expf(-0.01f * (curt - t.x));
        w.y = __expf(-0.01f * (curt - t.y));
        w.z = __expf(-0.01f * (curt - t.z));
        w.w = __expf(-0.01f * (curt - t.w));
        *reinterpret_cast<float4*>(g_tw + idx) = w;
    }
}

// ============================================================
// k_main: streaming pass over memory_bank. PER-WARP pipelines:
// each warp owns WDEPTH 4KB smem slots, issues/waits its own cp.async
// groups, no __syncthreads in the mainloop. Warp g (of 144 per b)
// streams 28-29 contiguous rows. Last CTA per b finalizes m and 1/E.
// ============================================================
__global__ __launch_bounds__(256, 2) void k_main(
    const float* __restrict__ mb, const float* __restrict__ query,
    const float* __restrict__ bq, const float* __restrict__ bk)
{
    extern __shared__ __align__(16) float4 sbuf[];   // 8 warps * 3 slots * 256 f4
    __shared__ float sE[8];
    __shared__ int sLast;

    int b = blockIdx.x / CTAS_PER_B;
    int j = blockIdx.x % CTAS_PER_B;
    int warp = threadIdx.x >> 5, lane = threadIdx.x & 31, tid = threadIdx.x;

    // warp-global index within b: 144 warps; 64x29 + 80x28 = 4096 rows
    int g = j * 8 + warp;
    int n  = (g < 64) ? 29 : 28;
    int s0 = (g < 64) ? g * 29 : 64 * 29 + (g - 64) * 28;

    const float4* rowbase = reinterpret_cast<const float4*>(mb) + (size_t)b * S * D4;
    uint32_t sb = (uint32_t)__cvta_generic_to_shared(sbuf);
    uint32_t wbase = sb + (uint32_t)warp * (WDEPTH * ROW_F4 * 16);

    // ---- prologue: each warp issues its first WDEPTH rows ----
#pragma unroll
    for (int r = 0; r < WDEPTH; r++) {
        const float4* src = rowbase + (size_t)(s0 + r) * D4;
        uint32_t dst = wbase + (uint32_t)r * (ROW_F4 * 16);
#pragma unroll
        for (int k = 0; k < 8; k++)
            cp_async16(dst + (uint32_t)(k * 32 + lane) * 16, src + k * 32 + lane);
        cp_commit();
    }

    // ---- qt split-reduce (overlaps DRAM ramp) ----
    float4 q[8];
#pragma unroll
    for (int k = 0; k < 8; k++) q[k] = make_float4(0.f, 0.f, 0.f, 0.f);
    for (int sp = 0; sp < QT_SPLITS; sp++) {
        const float4* qp = reinterpret_cast<const float4*>(g_qt_part)
                           + (size_t)(sp * B + b) * D4;
#pragma unroll
        for (int k = 0; k < 8; k++) {
            float4 v = qp[k * 32 + lane];
            q[k].x += v.x; q[k].y += v.y; q[k].z += v.z; q[k].w += v.w;
        }
    }
    // ---- qbk = query[b].u + bq.bk  (u = Wq^T.bk, 4 partials) ----
    const float4* X4 = reinterpret_cast<const float4*>(query) + b * D4;
    const float4* U4 = reinterpret_cast<const float4*>(g_u_part);
    const float4* bq4 = reinterpret_cast<const float4*>(bq);
    const float4* bk4 = reinterpret_cast<const float4*>(bk);
    float qb = 0.f;
#pragma unroll
    for (int k = 0; k < 8; k++) {
        int idx = k * 32 + lane;
        float4 u = U4[idx];
        float4 u1 = U4[D4 + idx], u2 = U4[2 * D4 + idx], u3 = U4[3 * D4 + idx];
        u.x += u1.x + u2.x + u3.x; u.y += u1.y + u2.y + u3.y;
        u.z += u1.z + u2.z + u3.z; u.w += u1.w + u2.w + u3.w;
        float4 x = X4[idx];
        qb += x.x * u.x + x.y * u.y + x.z * u.z + x.w * u.w;
        float4 a = bq4[idx], c = bk4[idx];
        qb += a.x * c.x + a.y * c.y + a.z * c.z + a.w * c.w;
    }
#pragma unroll
    for (int o = 16; o > 0; o >>= 1) qb += __shfl_xor_sync(0xffffffffu, qb, o);

    float4 acc[8];
#pragma unroll
    for (int k = 0; k < 8; k++) acc[k] = make_float4(0.f, 0.f, 0.f, 0.f);
    float Ew = 0.f;

    // ---- mainloop: no CTA barriers ----
    for (int i = 0; i < n; i++) {
        int s = s0 + i;
        float twv = g_tw[b * S + s];

        if (i < n - 2)       cp_wait<WDEPTH - 1>();
        else if (i == n - 2) cp_wait<1>();
        else                 cp_wait<0>();

        int slot = i % WDEPTH;
        const float4* vp = sbuf + (size_t)warp * (WDEPTH * ROW_F4) + slot * ROW_F4;
        float4 v[8];
#pragma unroll
        for (int k = 0; k < 8; k++) v[k] = vp[k * 32 + lane];

        // dot first (consumes v -> LDS complete before slot refill)
        float d0 = 0.f, d1 = 0.f, d2 = 0.f, d3 = 0.f;
#pragma unroll
        for (int k = 0; k < 8; k++) {
            d0 += v[k].x * q[k].x; d1 += v[k].y * q[k].y;
            d2 += v[k].z * q[k].z; d3 += v[k].w * q[k].w;
        }
        float ds = (d0 + d1) + (d2 + d3);

        // refill this slot with row i+WDEPTH before the long reduce/exp chain
        if (i + WDEPTH < n) {
            const float4* src = rowbase + (size_t)(s0 + i + WDEPTH) * D4;
            uint32_t dst = wbase + (uint32_t)slot * (ROW_F4 * 16);
#pragma unroll
            for (int k = 0; k < 8; k++)
                cp_async16(dst + (uint32_t)(k * 32 + lane) * 16, src + k * 32 + lane);
            cp_commit();
        }

#pragma unroll
        for (int o = 16; o > 0; o >>= 1) ds += __shfl_xor_sync(0xffffffffu, ds, o);
        float p = __expf((ds + qb) * 0.03125f * twv);
        if (lane == 0) g_p[b * S + s] = p;
        Ew += p;
#pragma unroll
        for (int k = 0; k < 8; k++) {
            acc[k].x += p * v[k].x; acc[k].y += p * v[k].y;
            acc[k].z += p * v[k].z; acc[k].w += p * v[k].w;
        }
    }

    // ---- epilogue: cross-warp reduce (reuse own smem slots) ----
    float4* red = sbuf;
#pragma unroll
    for (int k = 0; k < 8; k++)
        red[(size_t)warp * (WDEPTH * ROW_F4) + k * 32 + lane] = acc[k];
    if (lane == 0) sE[warp] = Ew;
    __syncthreads();

    float4 r = make_float4(0.f, 0.f, 0.f, 0.f);
#pragma unroll
    for (int w = 0; w < 8; w++) {
        float4 v = red[(size_t)w * (WDEPTH * ROW_F4) + tid];
        r.x += v.x; r.y += v.y; r.z += v.z; r.w += v.w;
    }
    reinterpret_cast<float4*>(g_macc)[(size_t)blockIdx.x * D4 + tid] = r;
    if (tid == 0) {
        float e = 0.f;
#pragma unroll
        for (int w = 0; w < 8; w++) e += sE[w];
        g_Epart[blockIdx.x] = e;
    }

    // ---- last CTA per b finalizes m = (sum macc)/E and 1/E (arrive-only) ----
    __threadfence();
    __syncthreads();
    if (tid == 0) sLast = (atomicAdd(&g_cnt[b], 1) == CTAS_PER_B - 1);
    __syncthreads();
    if (sLast) {
        __threadfence();
        const float4* mp = reinterpret_cast<const float4*>(g_macc);
        float4 a = make_float4(0.f, 0.f, 0.f, 0.f);
#pragma unroll
        for (int c = 0; c < CTAS_PER_B; c++) {
            float4 v = mp[(size_t)(b * CTAS_PER_B + c) * D4 + tid];
            a.x += v.x; a.y += v.y; a.z += v.z; a.w += v.w;
        }
        float Et = 0.f;
#pragma unroll
        for (int c = 0; c < CTAS_PER_B; c++) Et += g_Epart[b * CTAS_PER_B + c];
        float inv = 1.f / Et;
        a.x *= inv; a.y *= inv; a.z *= inv; a.w *= inv;
        reinterpret_cast<float4*>(g_m)[b * D4 + tid] = a;
        if (tid == 0) { g_inv[b] = inv; g_cnt[b] = 0; }
    }
}

// ============================================================
// k_post: 192 blocks.
//   bid 0..127  : attended[b,d] = m[b].Wv[d] + bv[d]  (m already /E)
//   bid 128..191: attn = p * (1/E)
// ============================================================
__global__ __launch_bounds__(256) void k_post(
    const float* __restrict__ Wv, const float* __restrict__ bv,
    float* __restrict__ attended, float* __restrict__ attn)
{
    int bid = blockIdx.x, tid = threadIdx.x;
    if (bid < 128) {
        int warp = tid >> 5, lane = tid & 31;
        int d = bid * 8 + warp;
        const float4* W4 = reinterpret_cast<const float4*>(Wv) + (size_t)d * D4;
        const float4* X4 = reinterpret_cast<const float4*>(g_m);
        float4 w[8];
#pragma unroll
        for (int k = 0; k < 8; k++) w[k] = W4[k * 32 + lane];
        float bb = bv[d];
#pragma unroll
        for (int b = 0; b < B; b += 2) {
            float sa = 0.f, sb = 0.f;
#pragma unroll
            for (int k = 0; k < 8; k++) {
                float4 xa = X4[b * D4 + k * 32 + lane];
                float4 xb = X4[(b + 1) * D4 + k * 32 + lane];
                sa += xa.x * w[k].x; sa += xa.y * w[k].y;
                sa += xa.z * w[k].z; sa += xa.w * w[k].w;
                sb += xb.x * w[k].x; sb += xb.y * w[k].y;
                sb += xb.z * w[k].z; sb += xb.w * w[k].w;
            }
#pragma unroll
            for (int o = 16; o > 0; o >>= 1) {
                sa += __shfl_xor_sync(0xffffffffu, sa, o);
                sb += __shfl_xor_sync(0xffffffffu, sb, o);
            }
            if (lane == 0) {
                attended[b * D + d] = sa + bb;
                attended[(b + 1) * D + d] = sb + bb;
            }
        }
    } else {
        int flat = (bid - 128) * 1024 + tid * 4;
        int b = flat >> 12;
        float inv = g_inv[b];
        float4 p = *reinterpret_cast<const float4*>(g_p + flat);
        p.x *= inv; p.y *= inv; p.z *= inv; p.w *= inv;
        *reinterpret_cast<float4*>(attn + flat) = p;
    }
}

// ============================================================
extern "C" void kernel_launch(void* const* d_in, const int* in_sizes, int n_in,
                              void* d_out, int out_size)
{
    const float* query = (const float*)d_in[0];
    const float* mb    = (const float*)d_in[1];
    const float* ts    = (const float*)d_in[2];
    const float* ct    = (const float*)d_in[3];
    const float* Wq    = (const float*)d_in[4];
    const float* bq    = (const float*)d_in[5];
    const float* Wk    = (const float*)d_in[6];
    const float* bk    = (const float*)d_in[7];
    const float* Wv    = (const float*)d_in[8];
    const float* bv    = (const float*)d_in[9];
    (void)in_sizes; (void)n_in; (void)out_size;

    float* attended = (float*)d_out;            // [16,1024]
    float* attn     = (float*)d_out + B * D;    // [16,4096]

    cudaFuncSetAttribute(k_main, cudaFuncAttributeMaxDynamicSharedMemorySize,
                         SMEM_MAIN);

    k_pre<<<144, 256>>>(query, Wq, bq, Wk, bk, ts, ct);   // qt + u + tw
    k_main<<<NCTA_MAIN, 256, SMEM_MAIN>>>(mb, query, bq, bk);  // 268 MB pass
    k_post<<<192, 256>>>(Wv, bv, attended, attn);         // attended + attn
}

// round 9
// speedup vs baseline: 1.1040x; 1.1040x over previous
#include <cuda_runtime.h>
#include <cstdint>

// CausalMemoryAttention: B=16, S=4096, D=1024   (exact restructure, validated)
//   Q = query@Wq^T + bq ; qt = Q@Wk ; qbk = query.(Wq^T.bk) + bq.bk
//   score[b,s] = (mb[b,s].qt[b] + qbk[b])/32 * tw[b,s],  tw = exp(-0.01*(ct-ts))
//   p = exp(score); attn = p/E; m = (sum p*mb)/E; attended = m@Wv^T + bv
// 5 launches:
//   k_q   (Q partials, shuffle-free transposed-smem GEMM; u = Wq^T.bk)
//   k_tw  (temporal weights)
//   k_qt  (Q reduce+bias fold -> qt partials, shuffle-free)
//   k_main(268MB pass, per-warp cp.async pipelines; last CTA per b -> m, 1/E)
//   k_post(attended GEMM + attn normalize)

#define B 16
#define S 4096
#define D 1024
#define D4 256
#define QT_SPLITS 16
#define CTAS_PER_B 18
#define NCTA_MAIN (B * CTAS_PER_B)        // 288 (single wave at 2 CTA/SM)
#define WDEPTH 3                          // per-warp pipeline depth (rows)
#define ROW_F4 256                        // one row = 4KB = 256 float4
#define SMEM_MAIN (8 * WDEPTH * ROW_F4 * 16)   // 96 KB

// -------- scratch (device globals; counter self-resets) --------
__device__ __align__(16) float g_q_part[16 * B * D];     // c-split Q partials
__device__ __align__(16) float g_qt_part[QT_SPLITS * B * D];
__device__ __align__(16) float g_u_part[4 * D];
__device__ __align__(16) float g_tw[B * S];
__device__ __align__(16) float g_p[B * S];
__device__ __align__(16) float g_macc[NCTA_MAIN * D];
__device__ float g_Epart[NCTA_MAIN];
__device__ __align__(16) float g_m[B * D];
__device__ float g_inv[B];
__device__ int g_cnt[B];      // k_main CTAs done per b (arrive-only, no spin)

// ---------------- cp.async helpers ----------------
// NOTE: "memory" clobber is load-bearing — the barrier-free mainloop relies on
// program order between the smem v[] loads and the same-slot cp.async refill.
__device__ __forceinline__ void cp_async16(uint32_t smem, const void* gmem) {
    asm volatile("cp.async.cg.shared.global [%0], [%1], 16;"
                 :: "r"(smem), "l"(gmem) : "memory");
}
__device__ __forceinline__ void cp_commit() {
    asm volatile("cp.async.commit_group;" ::: "memory");
}
template <int N> __device__ __forceinline__ void cp_wait() {
    asm volatile("cp.async.wait_group %0;" :: "n"(N) : "memory");
}

// ============================================================
// k_q: 144 blocks x 256 threads. Shuffle-free.
//   bid 0..127 : Q-partial role. block = (d-tile 128, c-chunk 64).
//     Stage Wq tile transposed in smem (pad 133: conflict-free), query
//     chunk in smem; thread owns one d-column x 8 batches in registers.
//     512 indep FMA/thread, no reductions. -> g_q_part[cs][b][d]
//   bid 128..143: u-role. u[e] partial = sum_{d in 256-chunk} Wq[d,e]*bk[d].
// ============================================================
__global__ __launch_bounds__(256) void k_q(
    const float* __restrict__ query, const float* __restrict__ Wq,
    const float* __restrict__ bk)
{
    int bid = blockIdx.x, tid = threadIdx.x;

    if (bid < 128) {
        __shared__ float wt[64 * 133];    // wt[c][d_local], pad 133
        __shared__ float qs[16 * 64];     // qs[b][c]
        int dt = bid & 7, cs = bid >> 3;
        int d0 = dt * 128, c0 = cs * 64;

        // load Wq tile [128 d x 64 c], transposed into smem
#pragma unroll
        for (int i = 0; i < 32; i++) {
            int row = i * 4 + (tid >> 6);   // d_local 0..127
            int col = tid & 63;             // c_local 0..63
            wt[col * 133 + row] = Wq[(size_t)(d0 + row) * D + c0 + col];
        }
        // load query chunk [16 b x 64 c]
        for (int i = tid; i < 1024; i += 256) {
            int b = i >> 6, c = i & 63;
            qs[b * 64 + c] = query[b * D + c0 + c];
        }
        __syncthreads();

        int dl = tid & 127;
        int bh = tid >> 7;                  // 0/1 -> batches 0..7 / 8..15
        float acc[8];
#pragma unroll
        for (int bb = 0; bb < 8; bb++) acc[bb] = 0.f;
#pragma unroll 4
        for (int c = 0; c < 64; c++) {
            float wv = wt[c * 133 + dl];
#pragma unroll
            for (int bb = 0; bb < 8; bb++)
                acc[bb] += qs[(bh * 8 + bb) * 64 + c] * wv;
        }
#pragma unroll
        for (int bb = 0; bb < 8; bb++)
            g_q_part[(size_t)cs * (B * D) + (bh * 8 + bb) * D + d0 + dl] = acc[bb];
    } else {
        // u-role: u[e] = sum_d Wq[d,e]*bk[d]  (d-split 4)
        int q = bid - 128;
        int e = (q & 3) * 256 + tid;
        int dp = q >> 2;
        int dbase = dp * 256;
        float s = 0.f;
#pragma unroll 8
        for (int d = 0; d < 256; d++)
            s += Wq[(size_t)(dbase + d) * D + e] * bk[dbase + d];
        g_u_part[dp * D + e] = s;
    }
}

// ============================================================
// k_tw: 64 blocks. tw = exp(-0.01*(ct-ts)).
// ============================================================
__global__ void k_tw(const float* __restrict__ ts, const float* __restrict__ ct)
{
    int idx = blockIdx.x * 1024 + threadIdx.x * 4;
    int b = idx >> 12;
    float curt = ct[b];
    float4 t = *reinterpret_cast<const float4*>(ts + idx);
    float4 w;
    w.x = __expf(-0.01f * (curt - t.x));
    w.y = __expf(-0.01f * (curt - t.y));
    w.z = __expf(-0.01f * (curt - t.z));
    w.w = __expf(-0.01f * (curt - t.w));
    *reinterpret_cast<float4*>(g_tw + idx) = w;
}

// ============================================================
// k_qt: 64 blocks x 256 threads. Shuffle-free.
//   block = (e-tile 256, d-chunk 64). On load: Q[b,d] = sum of 16
//   c-split partials + bq[d] -> smem Qs[dl][b] (pad 20). Then thread
//   per e: 64 x 16 FMA against coalesced Wk. -> g_qt_part[by][b][e]
// ============================================================
__global__ __launch_bounds__(256) void k_qt(
    const float* __restrict__ Wk, const float* __restrict__ bq)
{
    __shared__ float Qs[64 * 20];      // Qs[dl][b], pad 20
    int et = blockIdx.x & 3, by = blockIdx.x >> 2;
    int e = et * 256 + threadIdx.x;
    int d0 = by * 64;

    for (int i = threadIdx.x; i < 1024; i += 256) {
        int dl = i & 63, b = i >> 6;
        float s = bq[d0 + dl];
#pragma unroll
        for (int sp = 0; sp < 16; sp++)
            s += g_q_part[(size_t)sp * (B * D) + b * D + d0 + dl];
        Qs[dl * 20 + b] = s;
    }
    __syncthreads();

    float acc[16];
#pragma unroll
    for (int bb = 0; bb < 16; bb++) acc[bb] = 0.f;
#pragma unroll 4
    for (int dl = 0; dl < 64; dl++) {
        float wv = Wk[(size_t)(d0 + dl) * D + e];
        const float4* q4 = reinterpret_cast<const float4*>(&Qs[dl * 20]);
#pragma unroll
        for (int j = 0; j < 4; j++) {
            float4 qq = q4[j];
            acc[4 * j + 0] += qq.x * wv;
            acc[4 * j + 1] += qq.y * wv;
            acc[4 * j + 2] += qq.z * wv;
            acc[4 * j + 3] += qq.w * wv;
        }
    }
#pragma unroll
    for (int bb = 0; bb < 16; bb++)
        g_qt_part[(size_t)(by * 16 + bb) * D + e] = acc[bb];
}

// ============================================================
// k_main: streaming pass over memory_bank. PER-WARP pipelines:
// each warp owns WDEPTH 4KB smem slots, issues/waits its own cp.async
// groups, no __syncthreads in the mainloop. Warp g (of 144 per b)
// streams 28-29 contiguous rows. Last CTA per b finalizes m and 1/E.
// ============================================================
__global__ __launch_bounds__(256, 2) void k_main(
    const float* __restrict__ mb, const float* __restrict__ query,
    const float* __restrict__ bq, const float* __restrict__ bk)
{
    extern __shared__ __align__(16) float4 sbuf[];   // 8 warps * 3 slots * 256 f4
    __shared__ float sE[8];
    __shared__ int sLast;

    int b = blockIdx.x / CTAS_PER_B;
    int j = blockIdx.x % CTAS_PER_B;
    int warp = threadIdx.x >> 5, lane = threadIdx.x & 31, tid = threadIdx.x;

    // warp-global index within b: 144 warps; 64x29 + 80x28 = 4096 rows
    int g = j * 8 + warp;
    int n  = (g < 64) ? 29 : 28;
    int s0 = (g < 64) ? g * 29 : 64 * 29 + (g - 64) * 28;

    const float4* rowbase = reinterpret_cast<const float4*>(mb) + (size_t)b * S * D4;
    uint32_t sb = (uint32_t)__cvta_generic_to_shared(sbuf);
    uint32_t wbase = sb + (uint32_t)warp * (WDEPTH * ROW_F4 * 16);

    // ---- prologue: each warp issues its first WDEPTH rows ----
#pragma unroll
    for (int r = 0; r < WDEPTH; r++) {
        const float4* src = rowbase + (size_t)(s0 + r) * D4;
        uint32_t dst = wbase + (uint32_t)r * (ROW_F4 * 16);
#pragma unroll
        for (int k = 0; k < 8; k++)
            cp_async16(dst + (uint32_t)(k * 32 + lane) * 16, src + k * 32 + lane);
        cp_commit();
    }

    // ---- qt split-reduce (overlaps DRAM ramp) ----
    float4 q[8];
#pragma unroll
    for (int k = 0; k < 8; k++) q[k] = make_float4(0.f, 0.f, 0.f, 0.f);
    for (int sp = 0; sp < QT_SPLITS; sp++) {
        const float4* qp = reinterpret_cast<const float4*>(g_qt_part)
                           + (size_t)(sp * B + b) * D4;
#pragma unroll
        for (int k = 0; k < 8; k++) {
            float4 v = qp[k * 32 + lane];
            q[k].x += v.x; q[k].y += v.y; q[k].z += v.z; q[k].w += v.w;
        }
    }
    // ---- qbk = query[b].u + bq.bk  (u = Wq^T.bk, 4 partials) ----
    const float4* X4 = reinterpret_cast<const float4*>(query) + b * D4;
    const float4* U4 = reinterpret_cast<const float4*>(g_u_part);
    const float4* bq4 = reinterpret_cast<const float4*>(bq);
    const float4* bk4 = reinterpret_cast<const float4*>(bk);
    float qb = 0.f;
#pragma unroll
    for (int k = 0; k < 8; k++) {
        int idx = k * 32 + lane;
        float4 u = U4[idx];
        float4 u1 = U4[D4 + idx], u2 = U4[2 * D4 + idx], u3 = U4[3 * D4 + idx];
        u.x += u1.x + u2.x + u3.x; u.y += u1.y + u2.y + u3.y;
        u.z += u1.z + u2.z + u3.z; u.w += u1.w + u2.w + u3.w;
        float4 x = X4[idx];
        qb += x.x * u.x + x.y * u.y + x.z * u.z + x.w * u.w;
        float4 a = bq4[idx], c = bk4[idx];
        qb += a.x * c.x + a.y * c.y + a.z * c.z + a.w * c.w;
    }
#pragma unroll
    for (int o = 16; o > 0; o >>= 1) qb += __shfl_xor_sync(0xffffffffu, qb, o);

    float4 acc[8];
#pragma unroll
    for (int k = 0; k < 8; k++) acc[k] = make_float4(0.f, 0.f, 0.f, 0.f);
    float Ew = 0.f;

    // ---- mainloop: no CTA barriers ----
    for (int i = 0; i < n; i++) {
        int s = s0 + i;
        float twv = g_tw[b * S + s];

        if (i < n - 2)       cp_wait<WDEPTH - 1>();
        else if (i == n - 2) cp_wait<1>();
        else                 cp_wait<0>();

        int slot = i % WDEPTH;
        const float4* vp = sbuf + (size_t)warp * (WDEPTH * ROW_F4) + slot * ROW_F4;
        float4 v[8];
#pragma unroll
        for (int k = 0; k < 8; k++) v[k] = vp[k * 32 + lane];

        // dot first (consumes v -> LDS complete before slot refill)
        float d0 = 0.f, d1 = 0.f, d2 = 0.f, d3 = 0.f;
#pragma unroll
        for (int k = 0; k < 8; k++) {
            d0 += v[k].x * q[k].x; d1 += v[k].y * q[k].y;
            d2 += v[k].z * q[k].z; d3 += v[k].w * q[k].w;
        }
        float ds = (d0 + d1) + (d2 + d3);

        // refill this slot with row i+WDEPTH before the long reduce/exp chain
        if (i + WDEPTH < n) {
            const float4* src = rowbase + (size_t)(s0 + i + WDEPTH) * D4;
            uint32_t dst = wbase + (uint32_t)slot * (ROW_F4 * 16);
#pragma unroll
            for (int k = 0; k < 8; k++)
                cp_async16(dst + (uint32_t)(k * 32 + lane) * 16, src + k * 32 + lane);
            cp_commit();
        }

#pragma unroll
        for (int o = 16; o > 0; o >>= 1) ds += __shfl_xor_sync(0xffffffffu, ds, o);
        float p = __expf((ds + qb) * 0.03125f * twv);
        if (lane == 0) g_p[b * S + s] = p;
        Ew += p;
#pragma unroll
        for (int k = 0; k < 8; k++) {
            acc[k].x += p * v[k].x; acc[k].y += p * v[k].y;
            acc[k].z += p * v[k].z; acc[k].w += p * v[k].w;
        }
    }

    // ---- epilogue: cross-warp reduce (reuse own smem slots) ----
    float4* red = sbuf;
#pragma unroll
    for (int k = 0; k < 8; k++)
        red[(size_t)warp * (WDEPTH * ROW_F4) + k * 32 + lane] = acc[k];
    if (lane == 0) sE[warp] = Ew;
    __syncthreads();

    float4 r = make_float4(0.f, 0.f, 0.f, 0.f);
#pragma unroll
    for (int w = 0; w < 8; w++) {
        float4 v = red[(size_t)w * (WDEPTH * ROW_F4) + tid];
        r.x += v.x; r.y += v.y; r.z += v.z; r.w += v.w;
    }
    reinterpret_cast<float4*>(g_macc)[(size_t)blockIdx.x * D4 + tid] = r;
    if (tid == 0) {
        float e = 0.f;
#pragma unroll
        for (int w = 0; w < 8; w++) e += sE[w];
        g_Epart[blockIdx.x] = e;
    }

    // ---- last CTA per b finalizes m = (sum macc)/E and 1/E (arrive-only) ----
    __threadfence();
    __syncthreads();
    if (tid == 0) sLast = (atomicAdd(&g_cnt[b], 1) == CTAS_PER_B - 1);
    __syncthreads();
    if (sLast) {
        __threadfence();
        const float4* mp = reinterpret_cast<const float4*>(g_macc);
        float4 a = make_float4(0.f, 0.f, 0.f, 0.f);
#pragma unroll
        for (int c = 0; c < CTAS_PER_B; c++) {
            float4 v = mp[(size_t)(b * CTAS_PER_B + c) * D4 + tid];
            a.x += v.x; a.y += v.y; a.z += v.z; a.w += v.w;
        }
        float Et = 0.f;
#pragma unroll
        for (int c = 0; c < CTAS_PER_B; c++) Et += g_Epart[b * CTAS_PER_B + c];
        float inv = 1.f / Et;
        a.x *= inv; a.y *= inv; a.z *= inv; a.w *= inv;
        reinterpret_cast<float4*>(g_m)[b * D4 + tid] = a;
        if (tid == 0) { g_inv[b] = inv; g_cnt[b] = 0; }
    }
}

// ============================================================
// k_post: 192 blocks.
//   bid 0..127  : attended[b,d] = m[b].Wv[d] + bv[d]  (m already /E)
//   bid 128..191: attn = p * (1/E)
// ============================================================
__global__ __launch_bounds__(256) void k_post(
    const float* __restrict__ Wv, const float* __restrict__ bv,
    float* __restrict__ attended, float* __restrict__ attn)
{
    int bid = blockIdx.x, tid = threadIdx.x;
    if (bid < 128) {
        int warp = tid >> 5, lane = tid & 31;
        int d = bid * 8 + warp;
        const float4* W4 = reinterpret_cast<const float4*>(Wv) + (size_t)d * D4;
        const float4* X4 = reinterpret_cast<const float4*>(g_m);
        float4 w[8];
#pragma unroll
        for (int k = 0; k < 8; k++) w[k] = W4[k * 32 + lane];
        float bb = bv[d];
#pragma unroll
        for (int b = 0; b < B; b += 2) {
            float sa = 0.f, sb = 0.f;
#pragma unroll
            for (int k = 0; k < 8; k++) {
                float4 xa = X4[b * D4 + k * 32 + lane];
                float4 xb = X4[(b + 1) * D4 + k * 32 + lane];
                sa += xa.x * w[k].x; sa += xa.y * w[k].y;
                sa += xa.z * w[k].z; sa += xa.w * w[k].w;
                sb += xb.x * w[k].x; sb += xb.y * w[k].y;
                sb += xb.z * w[k].z; sb += xb.w * w[k].w;
            }
#pragma unroll
            for (int o = 16; o > 0; o >>= 1) {
                sa += __shfl_xor_sync(0xffffffffu, sa, o);
                sb += __shfl_xor_sync(0xffffffffu, sb, o);
            }
            if (lane == 0) {
                attended[b * D + d] = sa + bb;
                attended[(b + 1) * D + d] = sb + bb;
            }
        }
    } else {
        int flat = (bid - 128) * 1024 + tid * 4;
        int b = flat >> 12;
        float inv = g_inv[b];
        float4 p = *reinterpret_cast<const float4*>(g_p + flat);
        p.x *= inv; p.y *= inv; p.z *= inv; p.w *= inv;
        *reinterpret_cast<float4*>(attn + flat) = p;
    }
}

// ============================================================
extern "C" void kernel_launch(void* const* d_in, const int* in_sizes, int n_in,
                              void* d_out, int out_size)
{
    const float* query = (const float*)d_in[0];
    const float* mb    = (const float*)d_in[1];
    const float* ts    = (const float*)d_in[2];
    const float* ct    = (const float*)d_in[3];
    const float* Wq    = (const float*)d_in[4];
    const float* bq    = (const float*)d_in[5];
    const float* Wk    = (const float*)d_in[6];
    const float* bk    = (const float*)d_in[7];
    const float* Wv    = (const float*)d_in[8];
    const float* bv    = (const float*)d_in[9];
    (void)in_sizes; (void)n_in; (void)out_size;

    float* attended = (float*)d_out;            // [16,1024]
    float* attn     = (float*)d_out + B * D;    // [16,4096]

    cudaFuncSetAttribute(k_main, cudaFuncAttributeMaxDynamicSharedMemorySize,
                         SMEM_MAIN);

    k_q<<<144, 256>>>(query, Wq, bk);                     // 1: Q partials + u
    k_tw<<<64, 256>>>(ts, ct);                            // 2: tw
    k_qt<<<64, 256>>>(Wk, bq);                            // 3: qt partials
    k_main<<<NCTA_MAIN, 256, SMEM_MAIN>>>(mb, query, bq, bk);  // 4: 268 MB pass
    k_post<<<192, 256>>>(Wv, bv, attended, attn);         // 5: attended + attn
}